// round 13
// baseline (speedup 1.0000x reference)
#include <cuda_runtime.h>
#include <cuda_fp16.h>
#include <cstdint>

// Problem constants
#define BS      4096
#define Z_DIM   512
#define HID     1024
#define Z_IN    128
#define N_STEP  32
#define OUT_DIM 3
#define G3      (3*HID)        // 3072
#define X_DIM   (OUT_DIM+Z_IN) // 131

// Scratch (device globals — no allocation allowed)
__device__ float  g_h[BS * HID];       // exact hidden state (fp32)
__device__ __half g_hh_a[BS * HID];    // fp16 hidden, ping (GEMM A operand)
__device__ __half g_hh_b[BS * HID];    // fp16 hidden, pong
__device__ float  g_gi[BS * G3];       // z_in part of input gates (+b_ih)
__device__ float  g_zin[BS * Z_IN];
__device__ float  g_token[BS * OUT_DIM];   // fp32 token (epilogue, gate n)
__device__ __half g_tokx[BS * 16];     // A K-extension: [t0,t1,t2,0...] per row
__device__ __half g_Whx[G3 * 16];      // B K-ext: tokw for gates r,u; ZERO for gate n
__device__ float  g_tokwn[HID * 3];    // gate-n token weights (epilogue)
__device__ __half g_Wh[G3 * HID];      // fp16 W_hh

// ---------------------------------------------------------------------------
// helpers
// ---------------------------------------------------------------------------
__device__ __forceinline__ float to_tf32(float x) {
    uint32_t r;
    asm("cvt.rna.tf32.f32 %0, %1;" : "=r"(r) : "f"(x));
    return __uint_as_float(r);
}

__device__ __forceinline__ void mma_m16n8k8_tf32(float* c, const uint32_t* a, const uint32_t* b) {
    asm volatile(
        "mma.sync.aligned.m16n8k8.row.col.f32.tf32.tf32.f32 "
        "{%0,%1,%2,%3}, {%4,%5,%6,%7}, {%8,%9}, {%0,%1,%2,%3};\n"
        : "+f"(c[0]), "+f"(c[1]), "+f"(c[2]), "+f"(c[3])
        : "r"(a[0]), "r"(a[1]), "r"(a[2]), "r"(a[3]),
          "r"(b[0]), "r"(b[1]));
}

// fp16 MMA: m16n8k16, fp32 accumulate
__device__ __forceinline__ void mma_m16n8k16_f16(float* c, const uint32_t* a, const uint32_t* b) {
    asm volatile(
        "mma.sync.aligned.m16n8k16.row.col.f32.f16.f16.f32 "
        "{%0,%1,%2,%3}, {%4,%5,%6,%7}, {%8,%9}, {%0,%1,%2,%3};\n"
        : "+f"(c[0]), "+f"(c[1]), "+f"(c[2]), "+f"(c[3])
        : "r"(a[0]), "r"(a[1]), "r"(a[2]), "r"(a[3]),
          "r"(b[0]), "r"(b[1]));
}

// Exact activation for the output head (output-facing, tiny count)
__device__ __forceinline__ float sigmoidf(float x) {
    return 1.0f / (1.0f + expf(-x));
}

// Fast MUFU-based activations (round-11 win)
__device__ __forceinline__ float fast_exp(float x) {
    float r;
    asm("ex2.approx.f32 %0, %1;" : "=f"(r) : "f"(x * 1.4426950408889634f));
    return r;
}
__device__ __forceinline__ float fast_rcp(float x) {
    float r;
    asm("rcp.approx.f32 %0, %1;" : "=f"(r) : "f"(x));
    return r;
}
__device__ __forceinline__ float fast_sig(float x) {
    return fast_rcp(1.0f + fast_exp(-x));
}
__device__ __forceinline__ float fast_tanh(float x) {
    return 1.0f - 2.0f * fast_rcp(fast_exp(2.0f * x) + 1.0f);
}

__device__ __forceinline__ void cp16(uint32_t dst, const void* src) {
    asm volatile("cp.async.cg.shared.global [%0], [%1], 16;" :: "r"(dst), "l"(src));
}
#define CP_COMMIT() asm volatile("cp.async.commit_group;")
#define CP_WAIT(n)  asm volatile("cp.async.wait_group %0;" :: "n"(n))

// ---------------------------------------------------------------------------
// Prologue GEMM body (tf32): C[M,N] = A[M,K] * B[N,K]^T + bias[N]
// ---------------------------------------------------------------------------
#define BM 128
#define BN 128
#define BK 32

__device__ __forceinline__ void gemm_body(
    const float* __restrict__ A, int lda,
    const float* __restrict__ B, int ldb,
    const float* __restrict__ bias,
    float* __restrict__ C,
    __half* __restrict__ Cdup,
    int m0, int n0, int N, int K)
{
    __shared__ float As[BM][BK + 4];
    __shared__ float Bs[BN][BK + 4];

    const int tid  = threadIdx.x;
    const int lane = tid & 31;
    const int warp = tid >> 5;
    const int wm   = warp & 3;
    const int wn   = warp >> 2;
    const int gid  = lane >> 2;
    const int l4   = lane & 3;

    float acc[2][8][4];
#pragma unroll
    for (int mt = 0; mt < 2; mt++)
#pragma unroll
        for (int nt = 0; nt < 8; nt++)
#pragma unroll
            for (int i = 0; i < 4; i++) acc[mt][nt][i] = 0.0f;

    for (int kt = 0; kt < K; kt += BK) {
#pragma unroll
        for (int i = 0; i < 16; i++) {
            int e = tid + i * 256;
            int r = e >> 5, c = e & 31;
            As[r][c] = to_tf32(A[(size_t)(m0 + r) * lda + kt + c]);
        }
#pragma unroll
        for (int i = 0; i < 16; i++) {
            int e = tid + i * 256;
            int r = e >> 5, c = e & 31;
            Bs[r][c] = to_tf32(B[(size_t)(n0 + r) * ldb + kt + c]);
        }
        __syncthreads();

#pragma unroll
        for (int kk = 0; kk < BK; kk += 8) {
            uint32_t af[2][4], bf[8][2];
#pragma unroll
            for (int mt = 0; mt < 2; mt++) {
                int rb = wm * 32 + mt * 16 + gid;
                af[mt][0] = __float_as_uint(As[rb    ][kk + l4    ]);
                af[mt][1] = __float_as_uint(As[rb + 8][kk + l4    ]);
                af[mt][2] = __float_as_uint(As[rb    ][kk + l4 + 4]);
                af[mt][3] = __float_as_uint(As[rb + 8][kk + l4 + 4]);
            }
#pragma unroll
            for (int nt = 0; nt < 8; nt++) {
                int rb = wn * 64 + nt * 8 + gid;
                bf[nt][0] = __float_as_uint(Bs[rb][kk + l4    ]);
                bf[nt][1] = __float_as_uint(Bs[rb][kk + l4 + 4]);
            }
#pragma unroll
            for (int mt = 0; mt < 2; mt++)
#pragma unroll
                for (int nt = 0; nt < 8; nt++)
                    mma_m16n8k8_tf32(acc[mt][nt], af[mt], bf[nt]);
        }
        __syncthreads();
    }

#pragma unroll
    for (int mt = 0; mt < 2; mt++) {
#pragma unroll
        for (int nt = 0; nt < 8; nt++) {
            int row = m0 + wm * 32 + mt * 16 + gid;
            int col = n0 + wn * 64 + nt * 8 + l4 * 2;
            float b0 = bias[col], b1 = bias[col + 1];
            float v00 = acc[mt][nt][0] + b0;
            float v01 = acc[mt][nt][1] + b1;
            float v10 = acc[mt][nt][2] + b0;
            float v11 = acc[mt][nt][3] + b1;
            float* p0 = &C[(size_t)row * N + col];
            float* p1 = &C[(size_t)(row + 8) * N + col];
            p0[0] = v00; p0[1] = v01;
            p1[0] = v10; p1[1] = v11;
            if (Cdup) {
                *(half2*)&Cdup[(size_t)row * N + col]       = __floats2half2_rn(v00, v01);
                *(half2*)&Cdup[(size_t)(row + 8) * N + col] = __floats2half2_rn(v10, v11);
            }
        }
    }
}

// Generic prologue GEMM (used for gi)
__global__ void __launch_bounds__(256)
gemm_tf32(const float* __restrict__ A, int lda,
          const float* __restrict__ B, int ldb,
          const float* __restrict__ bias,
          float* __restrict__ C,
          __half* __restrict__ Cdup,
          int M, int N, int K)
{
    gemm_body(A, lda, B, ldb, bias, C, Cdup,
              blockIdx.y * BM, blockIdx.x * BN, N, K);
}

// Dual prologue GEMM: h0 (bx<8) and zin (bx==8) in one launch
__global__ void __launch_bounds__(256)
gemm_dual(const float* __restrict__ z,
          const float* __restrict__ W_zh, const float* __restrict__ b_zh,
          const float* __restrict__ W_zi, const float* __restrict__ b_zi,
          float* __restrict__ h0, __half* __restrict__ h0h,
          float* __restrict__ zin)
{
    const int bx = blockIdx.x;
    const int m0 = blockIdx.y * BM;
    if (bx < 8)
        gemm_body(z, Z_DIM, W_zh, Z_DIM, b_zh, h0, h0h, m0, bx * BN, HID, Z_DIM);
    else
        gemm_body(z, Z_DIM, W_zi, Z_DIM, b_zi, zin, nullptr, m0, 0, Z_IN, Z_DIM);
}

// ---------------------------------------------------------------------------
// Setup: token init, K-ext weights (r,u only; n zeroed), gate-n token weights,
//        W_hh fp16 conversion
// ---------------------------------------------------------------------------
__global__ void setup_kernel(const float* __restrict__ W_ih,
                             const float* __restrict__ W_hh,
                             const float* __restrict__ init_input)
{
    int i = blockIdx.x * blockDim.x + threadIdx.x;
    if (i < G3 * 16) {
        int rg = i >> 4, j = i & 15;
        // gates r,u get tokw in the K-extension; gate n rows stay ZERO
        // (gate n's token term lives OUTSIDE the r* product -> epilogue)
        g_Whx[i] = __float2half((j < 3 && rg < 2 * HID) ? W_ih[rg * X_DIM + j] : 0.0f);
    }
    if (i < HID * 3) {
        int u = i / 3, j = i - u * 3;
        g_tokwn[i] = W_ih[(size_t)(2 * HID + u) * X_DIM + j];
    }
    if (i < BS * 16) {
        int j = i & 15;
        g_tokx[i] = __float2half(j < 3 ? init_input[j] : 0.0f);
    }
    if (i < BS * OUT_DIM)
        g_token[i] = init_input[i % OUT_DIM];
    for (int j = i; j < G3 * HID; j += gridDim.x * blockDim.x)
        g_Wh[j] = __float2half(W_hh[j]);
}

// ---------------------------------------------------------------------------
// Fused step kernel: gh(+token corr for r,u via K-ext) = [h|tok]@[W_hh|tokw]^T
// fused with GRU update (gate n token corr in epilogue).
// fp16 m16n8k16, fp32 acc, scalar-LDS fragments.
// CTA: 128 rows x 64 units x 3 gates. 256 threads. 3-stage cp.async pipeline.
// ---------------------------------------------------------------------------
#define FBM 128
#define FBU 64
#define FBN 192
#define FBK 32                     // k-elements per staged tile
#define FSTH 40                    // row stride in halves (80 bytes; 16B-aligned)
#define NSTAGE 3
#define A_STG_B (FBM*FSTH*2)       // 10240 bytes per stage
#define B_STG_B (FBN*FSTH*2)       // 15360 bytes per stage
#define SB_OFF_B (NSTAGE*A_STG_B)                 // 30720
#define EXTA_OFF_B (SB_OFF_B + NSTAGE*B_STG_B)    // 76800
#define EXTB_OFF_B (EXTA_OFF_B + A_STG_B)         // 87040
#define SBH_OFF_B (EXTB_OFF_B + B_STG_B)          // 102400
#define STOK_OFF_B (SBH_OFF_B + FBN*4)            // 103168
#define STWN_OFF_B (STOK_OFF_B + FBM*3*4)         // 104704
#define FUSED_SMEM_BYTES (STWN_OFF_B + FBU*3*4)   // 105472

__global__ void __launch_bounds__(256)
fused_step(const __half* __restrict__ hsrc,  // fp16 h(t), read-only
           __half* __restrict__ hdst,        // fp16 h(t+1), write-only
           const float* __restrict__ b_hh)
{
    extern __shared__ char smemc[];
    float* s_bh  = (float*)(smemc + SBH_OFF_B);   // [g*64+u]
    float* s_tok = (float*)(smemc + STOK_OFF_B);  // [rloc*3+j]
    float* s_twn = (float*)(smemc + STWN_OFF_B);  // [u*3+j] (gate n only)

    const int n0  = blockIdx.x * FBU;
    const int m0  = blockIdx.y * FBM;
    const int tid = threadIdx.x;
    const int lane = tid & 31;
    const int warp = tid >> 5;
    const int wm = warp & 3;        // 4 warps along M (32 rows each)
    const int wn = warp >> 2;       // 2 warps along N (32 units each)
    const int gid = lane >> 2;
    const int l4  = lane & 3;

    uint32_t sbase = (uint32_t)__cvta_generic_to_shared(smemc);

    // ---- K-extension staging (once per kernel): A-ext 128x16, B-ext 192x16 ----
    {
        int r = tid >> 1, j = tid & 1;
        cp16(sbase + EXTA_OFF_B + (uint32_t)(r * (FSTH * 2) + j * 16),
             g_tokx + (size_t)(m0 + r) * 16 + j * 8);
        cp16(sbase + EXTB_OFF_B + (uint32_t)(r * (FSTH * 2) + j * 16),
             g_Whx + (size_t)((r >> 6) * HID + n0 + (r & 63)) * 16 + j * 8);
        if (tid < 128) {
            int e = tid + 256;
            int r2 = e >> 1, j2 = e & 1;
            cp16(sbase + EXTB_OFF_B + (uint32_t)(r2 * (FSTH * 2) + j2 * 16),
                 g_Whx + (size_t)((r2 >> 6) * HID + n0 + (r2 & 63)) * 16 + j2 * 8);
        }
    }
    CP_COMMIT();   // group: ext

    // per-thread cp.async coordinates for the k-tiles
    uint32_t adst[2]; const __half* asrc[2];
#pragma unroll
    for (int i = 0; i < 2; i++) {
        int e = tid + i * 256;          // 512 chunks: 128 rows x 4
        int r = e >> 2, j = e & 3;
        adst[i] = sbase + (uint32_t)(r * (FSTH * 2) + j * 16);
        asrc[i] = hsrc + (size_t)(m0 + r) * HID + j * 8;
    }
    uint32_t bdst[3]; const __half* bsrc[3];
#pragma unroll
    for (int i = 0; i < 3; i++) {
        int e = tid + i * 256;          // 768 chunks: 192 rows x 4
        int r = e >> 2, j = e & 3;
        bdst[i] = sbase + (uint32_t)(SB_OFF_B + r * (FSTH * 2) + j * 16);
        bsrc[i] = g_Wh + (size_t)((r >> 6) * HID + n0 + (r & 63)) * HID + j * 8;
    }

    auto issue = [&](int st, int kt) {
#pragma unroll
        for (int i = 0; i < 2; i++) cp16(adst[i] + (uint32_t)st * A_STG_B, asrc[i] + kt);
#pragma unroll
        for (int i = 0; i < 3; i++) cp16(bdst[i] + (uint32_t)st * B_STG_B, bsrc[i] + kt);
    };

    const int NKT = HID / FBK;   // 32

    // prologue: fill stages 0 and 1
    issue(0, 0);        CP_COMMIT();
    issue(1, FBK);      CP_COMMIT();

    // stage epilogue constants while loads fly
    if (tid < FBN) s_bh[tid] = b_hh[(tid >> 6) * HID + n0 + (tid & 63)];
    for (int e = tid; e < FBM * 3; e += 256) s_tok[e] = g_token[m0 * 3 + e];
    if (tid < FBU * 3) {
        int u = tid / 3, j = tid - u * 3;
        s_twn[tid] = g_tokwn[(size_t)(n0 + u) * 3 + j];
    }

    float acc[3][2][4][4];
#pragma unroll
    for (int g = 0; g < 3; g++)
#pragma unroll
        for (int mt = 0; mt < 2; mt++)
#pragma unroll
            for (int nt = 0; nt < 4; nt++)
#pragma unroll
                for (int i = 0; i < 4; i++) acc[g][mt][nt][i] = 0.0f;

    for (int it = 0; it < NKT; ++it) {
        CP_WAIT(1);                 // ext + stage it%3 ready
        __syncthreads();

        if (it == 0) {
            // K-extension MMA step (single k16): token correction for r,u
            const uint32_t* Aw = (const uint32_t*)(smemc + EXTA_OFF_B);
            const uint32_t* Bw = (const uint32_t*)(smemc + EXTB_OFF_B);
            uint32_t a[2][4];
#pragma unroll
            for (int mt = 0; mt < 2; mt++) {
                int rb = wm * 32 + mt * 16 + gid;
                a[mt][0] = Aw[rb * 20 + l4];
                a[mt][1] = Aw[(rb + 8) * 20 + l4];
                a[mt][2] = Aw[rb * 20 + l4 + 4];
                a[mt][3] = Aw[(rb + 8) * 20 + l4 + 4];
            }
#pragma unroll
            for (int g = 0; g < 2; g++)     // gate n ext rows are zero; skip g=2
#pragma unroll
                for (int nt = 0; nt < 4; nt++) {
                    int rb = g * 64 + wn * 32 + nt * 8 + gid;
                    uint32_t b[2];
                    b[0] = Bw[rb * 20 + l4];
                    b[1] = Bw[rb * 20 + l4 + 4];
                    mma_m16n8k16_f16(acc[g][0][nt], a[0], b);
                    mma_m16n8k16_f16(acc[g][1][nt], a[1], b);
                }
        }

        if (it + 2 < NKT) issue((it + 2) % NSTAGE, (it + 2) * FBK);
        CP_COMMIT();

        // word-level views of the staged tiles (2 halves per 32-bit word)
        const uint32_t* Aw = (const uint32_t*)(smemc + (it % NSTAGE) * A_STG_B);
        const uint32_t* Bw = (const uint32_t*)(smemc + SB_OFF_B + (it % NSTAGE) * B_STG_B);

#pragma unroll
        for (int ks = 0; ks < 2; ks++) {        // two k16 steps per 32-wide tile
            const int kw = ks * 8 + l4;         // word offset within row (FSTH/2=20 words)
            uint32_t a[2][4];
#pragma unroll
            for (int mt = 0; mt < 2; mt++) {
                int rb = wm * 32 + mt * 16 + gid;
                a[mt][0] = Aw[rb * 20 + kw];
                a[mt][1] = Aw[(rb + 8) * 20 + kw];
                a[mt][2] = Aw[rb * 20 + kw + 4];
                a[mt][3] = Aw[(rb + 8) * 20 + kw + 4];
            }
#pragma unroll
            for (int g = 0; g < 3; g++)
#pragma unroll
                for (int nt = 0; nt < 4; nt++) {
                    int rb = g * 64 + wn * 32 + nt * 8 + gid;
                    uint32_t b[2];
                    b[0] = Bw[rb * 20 + kw];
                    b[1] = Bw[rb * 20 + kw + 4];
                    mma_m16n8k16_f16(acc[g][0][nt], a[0], b);
                    mma_m16n8k16_f16(acc[g][1][nt], a[1], b);
                }
        }
    }

    // ---- epilogue: GRU update (r,u token corr in acc; gate-n corr here) ----
#pragma unroll
    for (int mt = 0; mt < 2; mt++) {
#pragma unroll
        for (int rs = 0; rs < 2; rs++) {
            int rloc = wm * 32 + mt * 16 + gid + rs * 8;
            int grow = m0 + rloc;
            float t0 = s_tok[rloc * 3 + 0];
            float t1 = s_tok[rloc * 3 + 1];
            float t2 = s_tok[rloc * 3 + 2];
            const float* gi = g_gi + (size_t)grow * G3;
            float*  hrow  = g_h  + (size_t)grow * HID;
            __half* hfrow = hdst + (size_t)grow * HID;
#pragma unroll
            for (int nt = 0; nt < 4; nt++) {
                int ul = wn * 32 + nt * 8 + l4 * 2;   // local unit (even)
                int gu = n0 + ul;
                float2 gr  = *(const float2*)(gi + gu);
                float2 gu2 = *(const float2*)(gi + HID + gu);
                float2 gn  = *(const float2*)(gi + 2 * HID + gu);
                float2 h2  = *(const float2*)(hrow + gu);

                float hn_out[2];
#pragma unroll
                for (int c = 0; c < 2; c++) {
                    int u = ul + c;
                    float acc_r = acc[0][mt][nt][rs * 2 + c];
                    float acc_u = acc[1][mt][nt][rs * 2 + c];
                    float acc_n = acc[2][mt][nt][rs * 2 + c];
                    float gi_r = (c ? gr.y  : gr.x);
                    float gi_u = (c ? gu2.y : gu2.x);
                    float gi_n = (c ? gn.y  : gn.x);
                    float hold = (c ? h2.y  : h2.x);

                    // gate n input part: token correction OUTSIDE the r* product
                    float in_ = gi_n + t0 * s_twn[u * 3 + 0]
                                     + t1 * s_twn[u * 3 + 1]
                                     + t2 * s_twn[u * 3 + 2];

                    float r  = fast_sig(gi_r + acc_r + s_bh[u]);
                    float uu = fast_sig(gi_u + acc_u + s_bh[64 + u]);
                    float n  = fast_tanh(in_ + r * (acc_n + s_bh[128 + u]));
                    hn_out[c] = (1.0f - uu) * n + uu * hold;
                }
                *(float2*)(hrow + gu) = make_float2(hn_out[0], hn_out[1]);
                *(half2*)(hfrow + gu) = __floats2half2_rn(hn_out[0], hn_out[1]);
            }
        }
    }
}

// ---------------------------------------------------------------------------
// Output head (per-row): o = h_new @ W_out^T + b_out; recon + next token.
// ---------------------------------------------------------------------------
__global__ void __launch_bounds__(128)
out_head(const float* __restrict__ W_out,
         const float* __restrict__ b_out,
         float* __restrict__ recon,
         int t)
{
    const int row = blockIdx.x;
    const int tid = threadIdx.x;
    const int lane = tid & 31;
    const int warp = tid >> 5;
    __shared__ float red[3][4];

    const float4* h4 = (const float4*)(g_h + (size_t)row * HID);
    const float4* w0 = (const float4*)(W_out);
    const float4* w1 = (const float4*)(W_out + HID);
    const float4* w2 = (const float4*)(W_out + 2 * HID);

    float s0 = 0.f, s1 = 0.f, s2 = 0.f;
#pragma unroll
    for (int i = 0; i < HID / (128 * 4); i++) {
        int idx = tid + i * 128;
        float4 hv = h4[idx];
        float4 a = w0[idx], b = w1[idx], c = w2[idx];
        s0 += hv.x * a.x + hv.y * a.y + hv.z * a.z + hv.w * a.w;
        s1 += hv.x * b.x + hv.y * b.y + hv.z * b.z + hv.w * b.w;
        s2 += hv.x * c.x + hv.y * c.y + hv.z * c.z + hv.w * c.w;
    }
#pragma unroll
    for (int off = 16; off > 0; off >>= 1) {
        s0 += __shfl_down_sync(0xffffffffu, s0, off);
        s1 += __shfl_down_sync(0xffffffffu, s1, off);
        s2 += __shfl_down_sync(0xffffffffu, s2, off);
    }
    if (lane == 0) { red[0][warp] = s0; red[1][warp] = s1; red[2][warp] = s2; }
    __syncthreads();
    if (tid == 0) {
        float a0 = red[0][0] + red[0][1] + red[0][2] + red[0][3];
        float a1 = red[1][0] + red[1][1] + red[1][2] + red[1][3];
        float a2 = red[2][0] + red[2][1] + red[2][2] + red[2][3];
        float bass    = sigmoidf(a0 + b_out[0]);
        float rhy_int = a1 + b_out[1];
        float rhy     = sigmoidf(a2 + b_out[2]);
        float tok2    = (rhy > 0.5f) ? 1.0f : 0.0f;

        float* rc = recon + (size_t)row * (N_STEP * OUT_DIM) + t * OUT_DIM;
        rc[0] = bass; rc[1] = rhy_int; rc[2] = rhy;

        // fp32 token (epilogue, gate n)
        g_token[row * 3 + 0] = bass;
        g_token[row * 3 + 1] = rhy_int;
        g_token[row * 3 + 2] = tok2;
        // fp16 token into K-extension buffer (cols 3..15 stay zero)
        __half* tk = g_tokx + (size_t)row * 16;
        tk[0] = __float2half(bass);
        tk[1] = __float2half(rhy_int);
        tk[2] = __float2half(tok2);
    }
}

// ---------------------------------------------------------------------------
// kernel_launch
// inputs: 0 z, 1 inference, 2 tfr, 3 W_zh, 4 b_zh, 5 W_zi, 6 b_zi,
//         7 W_ih, 8 b_ih, 9 W_hh, 10 b_hh, 11 W_out, 12 b_out, 13 init_input
// ---------------------------------------------------------------------------
extern "C" void kernel_launch(void* const* d_in, const int* in_sizes, int n_in,
                              void* d_out, int out_size)
{
    (void)in_sizes; (void)n_in; (void)out_size;

    const float* z      = (const float*)d_in[0];
    const float* W_zh   = (const float*)d_in[3];
    const float* b_zh   = (const float*)d_in[4];
    const float* W_zi   = (const float*)d_in[5];
    const float* b_zi   = (const float*)d_in[6];
    const float* W_ih   = (const float*)d_in[7];
    const float* b_ih   = (const float*)d_in[8];
    const float* W_hh   = (const float*)d_in[9];
    const float* b_hh   = (const float*)d_in[10];
    const float* W_out  = (const float*)d_in[11];
    const float* b_out  = (const float*)d_in[12];
    const float* initin = (const float*)d_in[13];
    float* recon = (float*)d_out;

    float *p_h, *p_gi, *p_zin;
    __half *p_ha, *p_hb;
    cudaGetSymbolAddress((void**)&p_h,   g_h);
    cudaGetSymbolAddress((void**)&p_gi,  g_gi);
    cudaGetSymbolAddress((void**)&p_zin, g_zin);
    cudaGetSymbolAddress((void**)&p_ha,  g_hh_a);
    cudaGetSymbolAddress((void**)&p_hb,  g_hh_b);

    cudaFuncSetAttribute(fused_step, cudaFuncAttributeMaxDynamicSharedMemorySize,
                         FUSED_SMEM_BYTES);

    // 1: setup (token, K-ext weights, gate-n tokw, W_hh fp16)
    setup_kernel<<<192, 256>>>(W_ih, W_hh, initin);
    // 2: h0 (+fp16 dup) and z_in in one dual launch
    gemm_dual<<<dim3(9, BS / BM), 256>>>(z, W_zh, b_zh, W_zi, b_zi, p_h, p_ha, p_zin);
    // 3: gi = z_in @ W_ih[:,3:]^T + b_ih
    gemm_tf32<<<dim3(G3 / BN, BS / BM), 256>>>(p_zin, Z_IN, W_ih + OUT_DIM, X_DIM, b_ih, p_gi, nullptr, BS, G3, Z_IN);

    // 4..: steps (launch #4 = fused_step -> lands in the ncu capture slot)
    for (int t = 0; t < N_STEP; t++) {
        const __half* hsrc = (t & 1) ? p_hb : p_ha;
        __half*       hdst = (t & 1) ? p_ha : p_hb;
        fused_step<<<dim3(HID / FBU, BS / FBM), 256, FUSED_SMEM_BYTES>>>(hsrc, hdst, b_hh);
        out_head<<<BS, 128>>>(W_out, b_out, recon, t);
    }
}

// round 14
// speedup vs baseline: 1.2156x; 1.2156x over previous
#include <cuda_runtime.h>
#include <cuda_fp16.h>
#include <cstdint>

// Problem constants
#define BS      4096
#define Z_DIM   512
#define HID     1024
#define Z_IN    128
#define N_STEP  32
#define OUT_DIM 3
#define G3      (3*HID)        // 3072
#define X_DIM   (OUT_DIM+Z_IN) // 131

// Scratch (device globals — no allocation allowed)
__device__ float  g_h[BS * HID];       // exact hidden state (fp32)
__device__ __half g_hh_a[BS * HID];    // fp16 hidden, ping (GEMM A operand)
__device__ __half g_hh_b[BS * HID];    // fp16 hidden, pong
__device__ float  g_gi[BS * G3];       // z_in part of input gates (+b_ih)
__device__ float  g_zin[BS * Z_IN];
__device__ float  g_token[BS * OUT_DIM];   // fp32 token (epilogue, gate n)
__device__ __half g_tokx[BS * 16];     // A K-extension: [t0,t1,t2,0...] per row
__device__ __half g_Whx[G3 * 16];      // B K-ext: tokw for gates r,u; ZERO for gate n
__device__ float  g_tokwn[HID * 3];    // gate-n token weights (epilogue)
__device__ __half g_Wh[G3 * HID];      // fp16 W_hh

// ---------------------------------------------------------------------------
// helpers
// ---------------------------------------------------------------------------
__device__ __forceinline__ float to_tf32(float x) {
    uint32_t r;
    asm("cvt.rna.tf32.f32 %0, %1;" : "=r"(r) : "f"(x));
    return __uint_as_float(r);
}

__device__ __forceinline__ void mma_m16n8k8_tf32(float* c, const uint32_t* a, const uint32_t* b) {
    asm volatile(
        "mma.sync.aligned.m16n8k8.row.col.f32.tf32.tf32.f32 "
        "{%0,%1,%2,%3}, {%4,%5,%6,%7}, {%8,%9}, {%0,%1,%2,%3};\n"
        : "+f"(c[0]), "+f"(c[1]), "+f"(c[2]), "+f"(c[3])
        : "r"(a[0]), "r"(a[1]), "r"(a[2]), "r"(a[3]),
          "r"(b[0]), "r"(b[1]));
}

// fp16 MMA: m16n8k16, fp32 accumulate
__device__ __forceinline__ void mma_m16n8k16_f16(float* c, const uint32_t* a, const uint32_t* b) {
    asm volatile(
        "mma.sync.aligned.m16n8k16.row.col.f32.f16.f16.f32 "
        "{%0,%1,%2,%3}, {%4,%5,%6,%7}, {%8,%9}, {%0,%1,%2,%3};\n"
        : "+f"(c[0]), "+f"(c[1]), "+f"(c[2]), "+f"(c[3])
        : "r"(a[0]), "r"(a[1]), "r"(a[2]), "r"(a[3]),
          "r"(b[0]), "r"(b[1]));
}

// Exact activation for the output head (output-facing, tiny count)
__device__ __forceinline__ float sigmoidf(float x) {
    return 1.0f / (1.0f + expf(-x));
}

// Fast MUFU-based activations (round-11 win)
__device__ __forceinline__ float fast_exp(float x) {
    float r;
    asm("ex2.approx.f32 %0, %1;" : "=f"(r) : "f"(x * 1.4426950408889634f));
    return r;
}
__device__ __forceinline__ float fast_rcp(float x) {
    float r;
    asm("rcp.approx.f32 %0, %1;" : "=f"(r) : "f"(x));
    return r;
}
__device__ __forceinline__ float fast_sig(float x) {
    return fast_rcp(1.0f + fast_exp(-x));
}
__device__ __forceinline__ float fast_tanh(float x) {
    return 1.0f - 2.0f * fast_rcp(fast_exp(2.0f * x) + 1.0f);
}

__device__ __forceinline__ void cp16(uint32_t dst, const void* src) {
    asm volatile("cp.async.cg.shared.global [%0], [%1], 16;" :: "r"(dst), "l"(src));
}
#define CP_COMMIT() asm volatile("cp.async.commit_group;")
#define CP_WAIT(n)  asm volatile("cp.async.wait_group %0;" :: "n"(n))

// ---------------------------------------------------------------------------
// Prologue GEMM body (tf32): C[M,N] = A[M,K] * B[N,K]^T + bias[N]
// ---------------------------------------------------------------------------
#define BM 128
#define BN 128
#define BK 32

__device__ __forceinline__ void gemm_body(
    const float* __restrict__ A, int lda,
    const float* __restrict__ B, int ldb,
    const float* __restrict__ bias,
    float* __restrict__ C,
    __half* __restrict__ Cdup,
    int m0, int n0, int N, int K)
{
    __shared__ float As[BM][BK + 4];
    __shared__ float Bs[BN][BK + 4];

    const int tid  = threadIdx.x;
    const int lane = tid & 31;
    const int warp = tid >> 5;
    const int wm   = warp & 3;
    const int wn   = warp >> 2;
    const int gid  = lane >> 2;
    const int l4   = lane & 3;

    float acc[2][8][4];
#pragma unroll
    for (int mt = 0; mt < 2; mt++)
#pragma unroll
        for (int nt = 0; nt < 8; nt++)
#pragma unroll
            for (int i = 0; i < 4; i++) acc[mt][nt][i] = 0.0f;

    for (int kt = 0; kt < K; kt += BK) {
#pragma unroll
        for (int i = 0; i < 16; i++) {
            int e = tid + i * 256;
            int r = e >> 5, c = e & 31;
            As[r][c] = to_tf32(A[(size_t)(m0 + r) * lda + kt + c]);
        }
#pragma unroll
        for (int i = 0; i < 16; i++) {
            int e = tid + i * 256;
            int r = e >> 5, c = e & 31;
            Bs[r][c] = to_tf32(B[(size_t)(n0 + r) * ldb + kt + c]);
        }
        __syncthreads();

#pragma unroll
        for (int kk = 0; kk < BK; kk += 8) {
            uint32_t af[2][4], bf[8][2];
#pragma unroll
            for (int mt = 0; mt < 2; mt++) {
                int rb = wm * 32 + mt * 16 + gid;
                af[mt][0] = __float_as_uint(As[rb    ][kk + l4    ]);
                af[mt][1] = __float_as_uint(As[rb + 8][kk + l4    ]);
                af[mt][2] = __float_as_uint(As[rb    ][kk + l4 + 4]);
                af[mt][3] = __float_as_uint(As[rb + 8][kk + l4 + 4]);
            }
#pragma unroll
            for (int nt = 0; nt < 8; nt++) {
                int rb = wn * 64 + nt * 8 + gid;
                bf[nt][0] = __float_as_uint(Bs[rb][kk + l4    ]);
                bf[nt][1] = __float_as_uint(Bs[rb][kk + l4 + 4]);
            }
#pragma unroll
            for (int mt = 0; mt < 2; mt++)
#pragma unroll
                for (int nt = 0; nt < 8; nt++)
                    mma_m16n8k8_tf32(acc[mt][nt], af[mt], bf[nt]);
        }
        __syncthreads();
    }

#pragma unroll
    for (int mt = 0; mt < 2; mt++) {
#pragma unroll
        for (int nt = 0; nt < 8; nt++) {
            int row = m0 + wm * 32 + mt * 16 + gid;
            int col = n0 + wn * 64 + nt * 8 + l4 * 2;
            float b0 = bias[col], b1 = bias[col + 1];
            float v00 = acc[mt][nt][0] + b0;
            float v01 = acc[mt][nt][1] + b1;
            float v10 = acc[mt][nt][2] + b0;
            float v11 = acc[mt][nt][3] + b1;
            float* p0 = &C[(size_t)row * N + col];
            float* p1 = &C[(size_t)(row + 8) * N + col];
            p0[0] = v00; p0[1] = v01;
            p1[0] = v10; p1[1] = v11;
            if (Cdup) {
                *(half2*)&Cdup[(size_t)row * N + col]       = __floats2half2_rn(v00, v01);
                *(half2*)&Cdup[(size_t)(row + 8) * N + col] = __floats2half2_rn(v10, v11);
            }
        }
    }
}

// Generic prologue GEMM (used for gi)
__global__ void __launch_bounds__(256)
gemm_tf32(const float* __restrict__ A, int lda,
          const float* __restrict__ B, int ldb,
          const float* __restrict__ bias,
          float* __restrict__ C,
          __half* __restrict__ Cdup,
          int M, int N, int K)
{
    gemm_body(A, lda, B, ldb, bias, C, Cdup,
              blockIdx.y * BM, blockIdx.x * BN, N, K);
}

// Dual prologue GEMM: h0 (bx<8) and zin (bx==8) in one launch
__global__ void __launch_bounds__(256)
gemm_dual(const float* __restrict__ z,
          const float* __restrict__ W_zh, const float* __restrict__ b_zh,
          const float* __restrict__ W_zi, const float* __restrict__ b_zi,
          float* __restrict__ h0, __half* __restrict__ h0h,
          float* __restrict__ zin)
{
    const int bx = blockIdx.x;
    const int m0 = blockIdx.y * BM;
    if (bx < 8)
        gemm_body(z, Z_DIM, W_zh, Z_DIM, b_zh, h0, h0h, m0, bx * BN, HID, Z_DIM);
    else
        gemm_body(z, Z_DIM, W_zi, Z_DIM, b_zi, zin, nullptr, m0, 0, Z_IN, Z_DIM);
}

// ---------------------------------------------------------------------------
// Setup: token init, K-ext weights (r,u only; n zeroed), gate-n token weights,
//        W_hh fp16 conversion
// ---------------------------------------------------------------------------
__global__ void setup_kernel(const float* __restrict__ W_ih,
                             const float* __restrict__ W_hh,
                             const float* __restrict__ init_input)
{
    int i = blockIdx.x * blockDim.x + threadIdx.x;
    if (i < G3 * 16) {
        int rg = i >> 4, j = i & 15;
        g_Whx[i] = __float2half((j < 3 && rg < 2 * HID) ? W_ih[rg * X_DIM + j] : 0.0f);
    }
    if (i < HID * 3) {
        int u = i / 3, j = i - u * 3;
        g_tokwn[i] = W_ih[(size_t)(2 * HID + u) * X_DIM + j];
    }
    if (i < BS * 16) {
        int j = i & 15;
        g_tokx[i] = __float2half(j < 3 ? init_input[j] : 0.0f);
    }
    if (i < BS * OUT_DIM)
        g_token[i] = init_input[i % OUT_DIM];
    for (int j = i; j < G3 * HID; j += gridDim.x * blockDim.x)
        g_Wh[j] = __float2half(W_hh[j]);
}

// ---------------------------------------------------------------------------
// Fused step kernel: 2 CTAs/SM to break the barrier convoy.
// CTA tile: 128 rows x 32 units x 3 gates (FBN=96). 256 threads (4M x 2N warps).
// Warp tile: 32 rows x 16 units x 3 gates -> acc = 48 regs.
// fp16 m16n8k16, fp32 acc, 3-stage cp.async. K-ext for gates r,u;
// gate-n token correction in epilogue.
// ---------------------------------------------------------------------------
#define FBM 128
#define FBU 32
#define FBN 96
#define FBK 32
#define FSTH 40                    // k-tile row stride in halves (80 B)
#define NSTAGE 3
#define A_STG_B (FBM*FSTH*2)       // 10240
#define B_STG_B (FBN*FSTH*2)       // 7680
#define SB_OFF_B (NSTAGE*A_STG_B)                 // 30720
#define EXTA_OFF_B (SB_OFF_B + NSTAGE*B_STG_B)    // 53760 (ext stride 32 B/row)
#define EXTB_OFF_B (EXTA_OFF_B + FBM*32)          // 57856
#define SBH_OFF_B (EXTB_OFF_B + FBN*32)           // 60928
#define STOK_OFF_B (SBH_OFF_B + FBN*4)            // 61312
#define STWN_OFF_B (STOK_OFF_B + FBM*3*4)         // 62848
#define FUSED_SMEM_BYTES (STWN_OFF_B + FBU*3*4)   // 63232 (~62 KB -> 2 CTAs/SM)

__global__ void __launch_bounds__(256, 2)
fused_step(const __half* __restrict__ hsrc,  // fp16 h(t), read-only
           __half* __restrict__ hdst,        // fp16 h(t+1), write-only
           const float* __restrict__ b_hh)
{
    extern __shared__ char smemc[];
    float* s_bh  = (float*)(smemc + SBH_OFF_B);   // [g*32+u]
    float* s_tok = (float*)(smemc + STOK_OFF_B);  // [rloc*3+j]
    float* s_twn = (float*)(smemc + STWN_OFF_B);  // [u*3+j] (gate n only)

    const int n0  = blockIdx.x * FBU;
    const int m0  = blockIdx.y * FBM;
    const int tid = threadIdx.x;
    const int lane = tid & 31;
    const int warp = tid >> 5;
    const int wm = warp & 3;        // 4 warps along M (32 rows each)
    const int wn = warp >> 2;       // 2 warps along N (16 units each)
    const int gid = lane >> 2;
    const int l4  = lane & 3;

    uint32_t sbase = (uint32_t)__cvta_generic_to_shared(smemc);

    // ---- K-extension staging (once): A-ext 128x16h, B-ext 96x16h; 32B rows ----
    {
        int r = tid >> 1, j = tid & 1;
        cp16(sbase + EXTA_OFF_B + (uint32_t)(r * 32 + j * 16),
             g_tokx + (size_t)(m0 + r) * 16 + j * 8);
        if (tid < 192)
            cp16(sbase + EXTB_OFF_B + (uint32_t)(r * 32 + j * 16),
                 g_Whx + (size_t)((r >> 5) * HID + n0 + (r & 31)) * 16 + j * 8);
    }
    CP_COMMIT();   // group: ext

    // per-thread cp.async coordinates for the k-tiles
    // A: 512 chunks (128 rows x 4) -> 2 per thread
    uint32_t adst[2]; const __half* asrc[2];
#pragma unroll
    for (int i = 0; i < 2; i++) {
        int e = tid + i * 256;
        int r = e >> 2, j = e & 3;
        adst[i] = sbase + (uint32_t)(r * (FSTH * 2) + j * 16);
        asrc[i] = hsrc + (size_t)(m0 + r) * HID + j * 8;
    }
    // B: 384 chunks (96 rows x 4) -> 1 per thread + tid<128 one more
    uint32_t bdst0, bdst1 = 0; const __half *bsrc0, *bsrc1 = nullptr;
    {
        int r = tid >> 2, j = tid & 3;
        bdst0 = sbase + (uint32_t)(SB_OFF_B + r * (FSTH * 2) + j * 16);
        bsrc0 = g_Wh + (size_t)((r >> 5) * HID + n0 + (r & 31)) * HID + j * 8;
        if (tid < 128) {
            int e = tid + 256;
            int r2 = e >> 2, j2 = e & 3;
            bdst1 = sbase + (uint32_t)(SB_OFF_B + r2 * (FSTH * 2) + j2 * 16);
            bsrc1 = g_Wh + (size_t)((r2 >> 5) * HID + n0 + (r2 & 31)) * HID + j2 * 8;
        }
    }

    auto issue = [&](int st, int kt) {
#pragma unroll
        for (int i = 0; i < 2; i++) cp16(adst[i] + (uint32_t)st * A_STG_B, asrc[i] + kt);
        cp16(bdst0 + (uint32_t)st * B_STG_B, bsrc0 + kt);
        if (bsrc1) cp16(bdst1 + (uint32_t)st * B_STG_B, bsrc1 + kt);
    };

    const int NKT = HID / FBK;   // 32

    // prologue: fill stages 0 and 1
    issue(0, 0);        CP_COMMIT();
    issue(1, FBK);      CP_COMMIT();

    // stage epilogue constants while loads fly
    if (tid < FBN) s_bh[tid] = b_hh[(tid >> 5) * HID + n0 + (tid & 31)];
    for (int e = tid; e < FBM * 3; e += 256) s_tok[e] = g_token[m0 * 3 + e];
    if (tid < FBU * 3) {
        int u = tid / 3, j = tid - u * 3;
        s_twn[tid] = g_tokwn[(size_t)(n0 + u) * 3 + j];
    }

    float acc[3][2][2][4];
#pragma unroll
    for (int g = 0; g < 3; g++)
#pragma unroll
        for (int mt = 0; mt < 2; mt++)
#pragma unroll
            for (int nt = 0; nt < 2; nt++)
#pragma unroll
                for (int i = 0; i < 4; i++) acc[g][mt][nt][i] = 0.0f;

    for (int it = 0; it < NKT; ++it) {
        CP_WAIT(1);
        __syncthreads();

        if (it == 0) {
            // K-extension MMA (single k16): token correction for gates r,u
            const uint32_t* Aw = (const uint32_t*)(smemc + EXTA_OFF_B);
            const uint32_t* Bw = (const uint32_t*)(smemc + EXTB_OFF_B);
            uint32_t a[2][4];
#pragma unroll
            for (int mt = 0; mt < 2; mt++) {
                int rb = wm * 32 + mt * 16 + gid;
                a[mt][0] = Aw[rb * 8 + l4];
                a[mt][1] = Aw[(rb + 8) * 8 + l4];
                a[mt][2] = Aw[rb * 8 + l4 + 4];
                a[mt][3] = Aw[(rb + 8) * 8 + l4 + 4];
            }
#pragma unroll
            for (int g = 0; g < 2; g++)     // gate n ext rows are zero; skip g=2
#pragma unroll
                for (int nt = 0; nt < 2; nt++) {
                    int rb = g * 32 + wn * 16 + nt * 8 + gid;
                    uint32_t b[2];
                    b[0] = Bw[rb * 8 + l4];
                    b[1] = Bw[rb * 8 + l4 + 4];
                    mma_m16n8k16_f16(acc[g][0][nt], a[0], b);
                    mma_m16n8k16_f16(acc[g][1][nt], a[1], b);
                }
        }

        if (it + 2 < NKT) issue((it + 2) % NSTAGE, (it + 2) * FBK);
        CP_COMMIT();

        const uint32_t* Aw = (const uint32_t*)(smemc + (it % NSTAGE) * A_STG_B);
        const uint32_t* Bw = (const uint32_t*)(smemc + SB_OFF_B + (it % NSTAGE) * B_STG_B);

#pragma unroll
        for (int ks = 0; ks < 2; ks++) {
            const int kw = ks * 8 + l4;     // word offset (FSTH/2 = 20 words/row)
            uint32_t a[2][4];
#pragma unroll
            for (int mt = 0; mt < 2; mt++) {
                int rb = wm * 32 + mt * 16 + gid;
                a[mt][0] = Aw[rb * 20 + kw];
                a[mt][1] = Aw[(rb + 8) * 20 + kw];
                a[mt][2] = Aw[rb * 20 + kw + 4];
                a[mt][3] = Aw[(rb + 8) * 20 + kw + 4];
            }
#pragma unroll
            for (int g = 0; g < 3; g++)
#pragma unroll
                for (int nt = 0; nt < 2; nt++) {
                    int rb = g * 32 + wn * 16 + nt * 8 + gid;
                    uint32_t b[2];
                    b[0] = Bw[rb * 20 + kw];
                    b[1] = Bw[rb * 20 + kw + 4];
                    mma_m16n8k16_f16(acc[g][0][nt], a[0], b);
                    mma_m16n8k16_f16(acc[g][1][nt], a[1], b);
                }
        }
    }

    // ---- epilogue: GRU update (r,u token corr in acc; gate-n corr here) ----
#pragma unroll
    for (int mt = 0; mt < 2; mt++) {
#pragma unroll
        for (int rs = 0; rs < 2; rs++) {
            int rloc = wm * 32 + mt * 16 + gid + rs * 8;
            int grow = m0 + rloc;
            float t0 = s_tok[rloc * 3 + 0];
            float t1 = s_tok[rloc * 3 + 1];
            float t2 = s_tok[rloc * 3 + 2];
            const float* gi = g_gi + (size_t)grow * G3;
            float*  hrow  = g_h  + (size_t)grow * HID;
            __half* hfrow = hdst + (size_t)grow * HID;
#pragma unroll
            for (int nt = 0; nt < 2; nt++) {
                int ul = wn * 16 + nt * 8 + l4 * 2;   // local unit (even)
                int gu = n0 + ul;
                float2 gr  = *(const float2*)(gi + gu);
                float2 gu2 = *(const float2*)(gi + HID + gu);
                float2 gn  = *(const float2*)(gi + 2 * HID + gu);
                float2 h2  = *(const float2*)(hrow + gu);

                float hn_out[2];
#pragma unroll
                for (int c = 0; c < 2; c++) {
                    int u = ul + c;
                    float acc_r = acc[0][mt][nt][rs * 2 + c];
                    float acc_u = acc[1][mt][nt][rs * 2 + c];
                    float acc_n = acc[2][mt][nt][rs * 2 + c];
                    float gi_r = (c ? gr.y  : gr.x);
                    float gi_u = (c ? gu2.y : gu2.x);
                    float gi_n = (c ? gn.y  : gn.x);
                    float hold = (c ? h2.y  : h2.x);

                    // gate n: token correction OUTSIDE the r* product
                    float in_ = gi_n + t0 * s_twn[u * 3 + 0]
                                     + t1 * s_twn[u * 3 + 1]
                                     + t2 * s_twn[u * 3 + 2];

                    float r  = fast_sig(gi_r + acc_r + s_bh[u]);
                    float uu = fast_sig(gi_u + acc_u + s_bh[32 + u]);
                    float n  = fast_tanh(in_ + r * (acc_n + s_bh[64 + u]));
                    hn_out[c] = (1.0f - uu) * n + uu * hold;
                }
                *(float2*)(hrow + gu) = make_float2(hn_out[0], hn_out[1]);
                *(half2*)(hfrow + gu) = __floats2half2_rn(hn_out[0], hn_out[1]);
            }
        }
    }
}

// ---------------------------------------------------------------------------
// Output head (per-row): o = h_new @ W_out^T + b_out; recon + next token.
// ---------------------------------------------------------------------------
__global__ void __launch_bounds__(128)
out_head(const float* __restrict__ W_out,
         const float* __restrict__ b_out,
         float* __restrict__ recon,
         int t)
{
    const int row = blockIdx.x;
    const int tid = threadIdx.x;
    const int lane = tid & 31;
    const int warp = tid >> 5;
    __shared__ float red[3][4];

    const float4* h4 = (const float4*)(g_h + (size_t)row * HID);
    const float4* w0 = (const float4*)(W_out);
    const float4* w1 = (const float4*)(W_out + HID);
    const float4* w2 = (const float4*)(W_out + 2 * HID);

    float s0 = 0.f, s1 = 0.f, s2 = 0.f;
#pragma unroll
    for (int i = 0; i < HID / (128 * 4); i++) {
        int idx = tid + i * 128;
        float4 hv = h4[idx];
        float4 a = w0[idx], b = w1[idx], c = w2[idx];
        s0 += hv.x * a.x + hv.y * a.y + hv.z * a.z + hv.w * a.w;
        s1 += hv.x * b.x + hv.y * b.y + hv.z * b.z + hv.w * b.w;
        s2 += hv.x * c.x + hv.y * c.y + hv.z * c.z + hv.w * c.w;
    }
#pragma unroll
    for (int off = 16; off > 0; off >>= 1) {
        s0 += __shfl_down_sync(0xffffffffu, s0, off);
        s1 += __shfl_down_sync(0xffffffffu, s1, off);
        s2 += __shfl_down_sync(0xffffffffu, s2, off);
    }
    if (lane == 0) { red[0][warp] = s0; red[1][warp] = s1; red[2][warp] = s2; }
    __syncthreads();
    if (tid == 0) {
        float a0 = red[0][0] + red[0][1] + red[0][2] + red[0][3];
        float a1 = red[1][0] + red[1][1] + red[1][2] + red[1][3];
        float a2 = red[2][0] + red[2][1] + red[2][2] + red[2][3];
        float bass    = sigmoidf(a0 + b_out[0]);
        float rhy_int = a1 + b_out[1];
        float rhy     = sigmoidf(a2 + b_out[2]);
        float tok2    = (rhy > 0.5f) ? 1.0f : 0.0f;

        float* rc = recon + (size_t)row * (N_STEP * OUT_DIM) + t * OUT_DIM;
        rc[0] = bass; rc[1] = rhy_int; rc[2] = rhy;

        g_token[row * 3 + 0] = bass;
        g_token[row * 3 + 1] = rhy_int;
        g_token[row * 3 + 2] = tok2;
        __half* tk = g_tokx + (size_t)row * 16;
        tk[0] = __float2half(bass);
        tk[1] = __float2half(rhy_int);
        tk[2] = __float2half(tok2);
    }
}

// ---------------------------------------------------------------------------
// kernel_launch
// inputs: 0 z, 1 inference, 2 tfr, 3 W_zh, 4 b_zh, 5 W_zi, 6 b_zi,
//         7 W_ih, 8 b_ih, 9 W_hh, 10 b_hh, 11 W_out, 12 b_out, 13 init_input
// ---------------------------------------------------------------------------
extern "C" void kernel_launch(void* const* d_in, const int* in_sizes, int n_in,
                              void* d_out, int out_size)
{
    (void)in_sizes; (void)n_in; (void)out_size;

    const float* z      = (const float*)d_in[0];
    const float* W_zh   = (const float*)d_in[3];
    const float* b_zh   = (const float*)d_in[4];
    const float* W_zi   = (const float*)d_in[5];
    const float* b_zi   = (const float*)d_in[6];
    const float* W_ih   = (const float*)d_in[7];
    const float* b_ih   = (const float*)d_in[8];
    const float* W_hh   = (const float*)d_in[9];
    const float* b_hh   = (const float*)d_in[10];
    const float* W_out  = (const float*)d_in[11];
    const float* b_out  = (const float*)d_in[12];
    const float* initin = (const float*)d_in[13];
    float* recon = (float*)d_out;

    float *p_h, *p_gi, *p_zin;
    __half *p_ha, *p_hb;
    cudaGetSymbolAddress((void**)&p_h,   g_h);
    cudaGetSymbolAddress((void**)&p_gi,  g_gi);
    cudaGetSymbolAddress((void**)&p_zin, g_zin);
    cudaGetSymbolAddress((void**)&p_ha,  g_hh_a);
    cudaGetSymbolAddress((void**)&p_hb,  g_hh_b);

    cudaFuncSetAttribute(fused_step, cudaFuncAttributeMaxDynamicSharedMemorySize,
                         FUSED_SMEM_BYTES);

    // 1: setup (token, K-ext weights, gate-n tokw, W_hh fp16)
    setup_kernel<<<192, 256>>>(W_ih, W_hh, initin);
    // 2: h0 (+fp16 dup) and z_in in one dual launch
    gemm_dual<<<dim3(9, BS / BM), 256>>>(z, W_zh, b_zh, W_zi, b_zi, p_h, p_ha, p_zin);
    // 3: gi = z_in @ W_ih[:,3:]^T + b_ih
    gemm_tf32<<<dim3(G3 / BN, BS / BM), 256>>>(p_zin, Z_IN, W_ih + OUT_DIM, X_DIM, b_ih, p_gi, nullptr, BS, G3, Z_IN);

    // 4..: steps (launch #4 = fused_step -> ncu capture slot)
    for (int t = 0; t < N_STEP; t++) {
        const __half* hsrc = (t & 1) ? p_hb : p_ha;
        __half*       hdst = (t & 1) ? p_ha : p_hb;
        fused_step<<<dim3(HID / FBU, BS / FBM), 256, FUSED_SMEM_BYTES>>>(hsrc, hdst, b_hh);
        out_head<<<BS, 128>>>(W_out, b_out, recon, t);
    }
}

// round 15
// speedup vs baseline: 1.2738x; 1.0479x over previous
#include <cuda_runtime.h>
#include <cuda_fp16.h>
#include <cstdint>

// Problem constants
#define BS      4096
#define Z_DIM   512
#define HID     1024
#define Z_IN    128
#define N_STEP  32
#define OUT_DIM 3
#define G3      (3*HID)        // 3072
#define X_DIM   (OUT_DIM+Z_IN) // 131

// Scratch (device globals — no allocation allowed)
__device__ float  g_h[BS * HID];       // exact hidden state (fp32)
__device__ __half g_hh_a[BS * HID];    // fp16 hidden, ping (GEMM A operand)
__device__ __half g_hh_b[BS * HID];    // fp16 hidden, pong
__device__ float  g_gi[BS * G3];       // z_in part of input gates (+b_ih)
__device__ float  g_zin[BS * Z_IN];
__device__ float  g_token[BS * OUT_DIM];   // fp32 token (epilogue, gate n)
__device__ __half g_tokx[BS * 16];     // A K-extension: [t0,t1,t2,0...] per row
__device__ __half g_Whx[G3 * 16];      // B K-ext: tokw for gates r,u; ZERO for gate n
__device__ float  g_tokwn[HID * 3];    // gate-n token weights (epilogue)
__device__ __half g_Wh[G3 * HID];      // fp16 W_hh

// ---------------------------------------------------------------------------
// helpers
// ---------------------------------------------------------------------------
__device__ __forceinline__ float to_tf32(float x) {
    uint32_t r;
    asm("cvt.rna.tf32.f32 %0, %1;" : "=r"(r) : "f"(x));
    return __uint_as_float(r);
}

__device__ __forceinline__ void mma_m16n8k8_tf32(float* c, const uint32_t* a, const uint32_t* b) {
    asm volatile(
        "mma.sync.aligned.m16n8k8.row.col.f32.tf32.tf32.f32 "
        "{%0,%1,%2,%3}, {%4,%5,%6,%7}, {%8,%9}, {%0,%1,%2,%3};\n"
        : "+f"(c[0]), "+f"(c[1]), "+f"(c[2]), "+f"(c[3])
        : "r"(a[0]), "r"(a[1]), "r"(a[2]), "r"(a[3]),
          "r"(b[0]), "r"(b[1]));
}

// fp16 MMA: m16n8k16, fp32 accumulate
__device__ __forceinline__ void mma_m16n8k16_f16(float* c, const uint32_t* a, const uint32_t* b) {
    asm volatile(
        "mma.sync.aligned.m16n8k16.row.col.f32.f16.f16.f32 "
        "{%0,%1,%2,%3}, {%4,%5,%6,%7}, {%8,%9}, {%0,%1,%2,%3};\n"
        : "+f"(c[0]), "+f"(c[1]), "+f"(c[2]), "+f"(c[3])
        : "r"(a[0]), "r"(a[1]), "r"(a[2]), "r"(a[3]),
          "r"(b[0]), "r"(b[1]));
}

// Exact activation for the output head (output-facing, tiny count)
__device__ __forceinline__ float sigmoidf(float x) {
    return 1.0f / (1.0f + expf(-x));
}

// Fast MUFU-based activations (round-11 win)
__device__ __forceinline__ float fast_exp(float x) {
    float r;
    asm("ex2.approx.f32 %0, %1;" : "=f"(r) : "f"(x * 1.4426950408889634f));
    return r;
}
__device__ __forceinline__ float fast_rcp(float x) {
    float r;
    asm("rcp.approx.f32 %0, %1;" : "=f"(r) : "f"(x));
    return r;
}
__device__ __forceinline__ float fast_sig(float x) {
    return fast_rcp(1.0f + fast_exp(-x));
}
__device__ __forceinline__ float fast_tanh(float x) {
    return 1.0f - 2.0f * fast_rcp(fast_exp(2.0f * x) + 1.0f);
}

__device__ __forceinline__ void cp16(uint32_t dst, const void* src) {
    asm volatile("cp.async.cg.shared.global [%0], [%1], 16;" :: "r"(dst), "l"(src));
}
#define CP_COMMIT() asm volatile("cp.async.commit_group;")
#define CP_WAIT(n)  asm volatile("cp.async.wait_group %0;" :: "n"(n))

// ---------------------------------------------------------------------------
// Prologue GEMM body (tf32): C[M,N] = A[M,K] * B[N,K]^T + bias[N]
// ---------------------------------------------------------------------------
#define BM 128
#define BN 128
#define BK 32

__device__ __forceinline__ void gemm_body(
    const float* __restrict__ A, int lda,
    const float* __restrict__ B, int ldb,
    const float* __restrict__ bias,
    float* __restrict__ C,
    __half* __restrict__ Cdup,
    int m0, int n0, int N, int K)
{
    __shared__ float As[BM][BK + 4];
    __shared__ float Bs[BN][BK + 4];

    const int tid  = threadIdx.x;
    const int lane = tid & 31;
    const int warp = tid >> 5;
    const int wm   = warp & 3;
    const int wn   = warp >> 2;
    const int gid  = lane >> 2;
    const int l4   = lane & 3;

    float acc[2][8][4];
#pragma unroll
    for (int mt = 0; mt < 2; mt++)
#pragma unroll
        for (int nt = 0; nt < 8; nt++)
#pragma unroll
            for (int i = 0; i < 4; i++) acc[mt][nt][i] = 0.0f;

    for (int kt = 0; kt < K; kt += BK) {
#pragma unroll
        for (int i = 0; i < 16; i++) {
            int e = tid + i * 256;
            int r = e >> 5, c = e & 31;
            As[r][c] = to_tf32(A[(size_t)(m0 + r) * lda + kt + c]);
        }
#pragma unroll
        for (int i = 0; i < 16; i++) {
            int e = tid + i * 256;
            int r = e >> 5, c = e & 31;
            Bs[r][c] = to_tf32(B[(size_t)(n0 + r) * ldb + kt + c]);
        }
        __syncthreads();

#pragma unroll
        for (int kk = 0; kk < BK; kk += 8) {
            uint32_t af[2][4], bf[8][2];
#pragma unroll
            for (int mt = 0; mt < 2; mt++) {
                int rb = wm * 32 + mt * 16 + gid;
                af[mt][0] = __float_as_uint(As[rb    ][kk + l4    ]);
                af[mt][1] = __float_as_uint(As[rb + 8][kk + l4    ]);
                af[mt][2] = __float_as_uint(As[rb    ][kk + l4 + 4]);
                af[mt][3] = __float_as_uint(As[rb + 8][kk + l4 + 4]);
            }
#pragma unroll
            for (int nt = 0; nt < 8; nt++) {
                int rb = wn * 64 + nt * 8 + gid;
                bf[nt][0] = __float_as_uint(Bs[rb][kk + l4    ]);
                bf[nt][1] = __float_as_uint(Bs[rb][kk + l4 + 4]);
            }
#pragma unroll
            for (int mt = 0; mt < 2; mt++)
#pragma unroll
                for (int nt = 0; nt < 8; nt++)
                    mma_m16n8k8_tf32(acc[mt][nt], af[mt], bf[nt]);
        }
        __syncthreads();
    }

#pragma unroll
    for (int mt = 0; mt < 2; mt++) {
#pragma unroll
        for (int nt = 0; nt < 8; nt++) {
            int row = m0 + wm * 32 + mt * 16 + gid;
            int col = n0 + wn * 64 + nt * 8 + l4 * 2;
            float b0 = bias[col], b1 = bias[col + 1];
            float v00 = acc[mt][nt][0] + b0;
            float v01 = acc[mt][nt][1] + b1;
            float v10 = acc[mt][nt][2] + b0;
            float v11 = acc[mt][nt][3] + b1;
            float* p0 = &C[(size_t)row * N + col];
            float* p1 = &C[(size_t)(row + 8) * N + col];
            p0[0] = v00; p0[1] = v01;
            p1[0] = v10; p1[1] = v11;
            if (Cdup) {
                *(half2*)&Cdup[(size_t)row * N + col]       = __floats2half2_rn(v00, v01);
                *(half2*)&Cdup[(size_t)(row + 8) * N + col] = __floats2half2_rn(v10, v11);
            }
        }
    }
}

// Generic prologue GEMM (used for gi)
__global__ void __launch_bounds__(256)
gemm_tf32(const float* __restrict__ A, int lda,
          const float* __restrict__ B, int ldb,
          const float* __restrict__ bias,
          float* __restrict__ C,
          __half* __restrict__ Cdup,
          int M, int N, int K)
{
    gemm_body(A, lda, B, ldb, bias, C, Cdup,
              blockIdx.y * BM, blockIdx.x * BN, N, K);
}

// Dual prologue GEMM: h0 (bx<8) and zin (bx==8) in one launch
__global__ void __launch_bounds__(256)
gemm_dual(const float* __restrict__ z,
          const float* __restrict__ W_zh, const float* __restrict__ b_zh,
          const float* __restrict__ W_zi, const float* __restrict__ b_zi,
          float* __restrict__ h0, __half* __restrict__ h0h,
          float* __restrict__ zin)
{
    const int bx = blockIdx.x;
    const int m0 = blockIdx.y * BM;
    if (bx < 8)
        gemm_body(z, Z_DIM, W_zh, Z_DIM, b_zh, h0, h0h, m0, bx * BN, HID, Z_DIM);
    else
        gemm_body(z, Z_DIM, W_zi, Z_DIM, b_zi, zin, nullptr, m0, 0, Z_IN, Z_DIM);
}

// ---------------------------------------------------------------------------
// Setup: token init, K-ext weights (r,u only; n zeroed), gate-n token weights,
//        W_hh fp16 conversion
// ---------------------------------------------------------------------------
__global__ void setup_kernel(const float* __restrict__ W_ih,
                             const float* __restrict__ W_hh,
                             const float* __restrict__ init_input)
{
    int i = blockIdx.x * blockDim.x + threadIdx.x;
    if (i < G3 * 16) {
        int rg = i >> 4, j = i & 15;
        g_Whx[i] = __float2half((j < 3 && rg < 2 * HID) ? W_ih[rg * X_DIM + j] : 0.0f);
    }
    if (i < HID * 3) {
        int u = i / 3, j = i - u * 3;
        g_tokwn[i] = W_ih[(size_t)(2 * HID + u) * X_DIM + j];
    }
    if (i < BS * 16) {
        int j = i & 15;
        g_tokx[i] = __float2half(j < 3 ? init_input[j] : 0.0f);
    }
    if (i < BS * OUT_DIM)
        g_token[i] = init_input[i % OUT_DIM];
    for (int j = i; j < G3 * HID; j += gridDim.x * blockDim.x)
        g_Wh[j] = __float2half(W_hh[j]);
}

// ---------------------------------------------------------------------------
// Fused step kernel: 3 CTAs/SM target (reg cap 85, 32-bit global offsets).
// CTA tile: 128 rows x 32 units x 3 gates (FBN=96). 256 threads (4M x 2N warps).
// fp16 m16n8k16, fp32 acc, 3-stage cp.async. K-ext for gates r,u;
// gate-n token correction in epilogue.
// ---------------------------------------------------------------------------
#define FBM 128
#define FBU 32
#define FBN 96
#define FBK 32
#define FSTH 40                    // k-tile row stride in halves (80 B)
#define NSTAGE 3
#define A_STG_B (FBM*FSTH*2)       // 10240
#define B_STG_B (FBN*FSTH*2)       // 7680
#define SB_OFF_B (NSTAGE*A_STG_B)                 // 30720
#define EXTA_OFF_B (SB_OFF_B + NSTAGE*B_STG_B)    // 53760 (ext stride 32 B/row)
#define EXTB_OFF_B (EXTA_OFF_B + FBM*32)          // 57856
#define SBH_OFF_B (EXTB_OFF_B + FBN*32)           // 60928
#define STOK_OFF_B (SBH_OFF_B + FBN*4)            // 61312
#define STWN_OFF_B (STOK_OFF_B + FBM*3*4)         // 62848
#define FUSED_SMEM_BYTES (STWN_OFF_B + FBU*3*4)   // 63232 (3x = 189.7 KB/SM)

__global__ void __launch_bounds__(256, 3)
fused_step(const __half* __restrict__ hsrc,  // fp16 h(t), read-only
           __half* __restrict__ hdst,        // fp16 h(t+1), write-only
           const float* __restrict__ b_hh)
{
    extern __shared__ char smemc[];
    float* s_bh  = (float*)(smemc + SBH_OFF_B);   // [g*32+u]
    float* s_tok = (float*)(smemc + STOK_OFF_B);  // [rloc*3+j]
    float* s_twn = (float*)(smemc + STWN_OFF_B);  // [u*3+j] (gate n only)

    const int n0  = blockIdx.x * FBU;
    const int m0  = blockIdx.y * FBM;
    const int tid = threadIdx.x;
    const int lane = tid & 31;
    const int warp = tid >> 5;
    const int wm = warp & 3;        // 4 warps along M (32 rows each)
    const int wn = warp >> 2;       // 2 warps along N (16 units each)
    const int gid = lane >> 2;
    const int l4  = lane & 3;

    uint32_t sbase = (uint32_t)__cvta_generic_to_shared(smemc);

    // ---- K-extension staging (once): A-ext 128x16h, B-ext 96x16h; 32B rows ----
    {
        int r = tid >> 1, j = tid & 1;
        cp16(sbase + EXTA_OFF_B + (uint32_t)(r * 32 + j * 16),
             g_tokx + (size_t)(m0 + r) * 16 + j * 8);
        if (tid < 192)
            cp16(sbase + EXTB_OFF_B + (uint32_t)(r * 32 + j * 16),
                 g_Whx + (size_t)((r >> 5) * HID + n0 + (r & 31)) * 16 + j * 8);
    }
    CP_COMMIT();   // group: ext

    // ---- per-thread cp.async coordinates: 32-bit element offsets only ----
    // A: 512 chunks (128 rows x 4) -> 2 per thread
    uint32_t adst[2], aoff[2];
#pragma unroll
    for (int i = 0; i < 2; i++) {
        int e = tid + i * 256;
        int r = e >> 2, j = e & 3;
        adst[i] = sbase + (uint32_t)(r * (FSTH * 2) + j * 16);
        aoff[i] = (uint32_t)((m0 + r) * HID + j * 8);
    }
    // B: 384 chunks (96 rows x 4) -> 1 per thread + tid<128 one more
    uint32_t bdst0, bdst1 = 0, boff0, boff1 = 0;
    {
        int r = tid >> 2, j = tid & 3;
        bdst0 = sbase + (uint32_t)(SB_OFF_B + r * (FSTH * 2) + j * 16);
        boff0 = (uint32_t)(((r >> 5) * HID + n0 + (r & 31)) * HID + j * 8);
        if (tid < 128) {
            int e = tid + 256;
            int r2 = e >> 2, j2 = e & 3;
            bdst1 = sbase + (uint32_t)(SB_OFF_B + r2 * (FSTH * 2) + j2 * 16);
            boff1 = (uint32_t)(((r2 >> 5) * HID + n0 + (r2 & 31)) * HID + j2 * 8);
        }
    }
    const bool hasB1 = (tid < 128);

    auto issue = [&](int st, int kt) {
#pragma unroll
        for (int i = 0; i < 2; i++)
            cp16(adst[i] + (uint32_t)st * A_STG_B, hsrc + aoff[i] + kt);
        cp16(bdst0 + (uint32_t)st * B_STG_B, g_Wh + boff0 + kt);
        if (hasB1) cp16(bdst1 + (uint32_t)st * B_STG_B, g_Wh + boff1 + kt);
    };

    const int NKT = HID / FBK;   // 32

    // prologue: fill stages 0 and 1
    issue(0, 0);        CP_COMMIT();
    issue(1, FBK);      CP_COMMIT();

    // stage epilogue constants while loads fly
    if (tid < FBN) s_bh[tid] = b_hh[(tid >> 5) * HID + n0 + (tid & 31)];
    for (int e = tid; e < FBM * 3; e += 256) s_tok[e] = g_token[m0 * 3 + e];
    if (tid < FBU * 3) {
        int u = tid / 3, j = tid - u * 3;
        s_twn[tid] = g_tokwn[(size_t)(n0 + u) * 3 + j];
    }

    float acc[3][2][2][4];
#pragma unroll
    for (int g = 0; g < 3; g++)
#pragma unroll
        for (int mt = 0; mt < 2; mt++)
#pragma unroll
            for (int nt = 0; nt < 2; nt++)
#pragma unroll
                for (int i = 0; i < 4; i++) acc[g][mt][nt][i] = 0.0f;

    for (int it = 0; it < NKT; ++it) {
        CP_WAIT(1);
        __syncthreads();

        if (it == 0) {
            // K-extension MMA (single k16): token correction for gates r,u
            const uint32_t* Aw = (const uint32_t*)(smemc + EXTA_OFF_B);
            const uint32_t* Bw = (const uint32_t*)(smemc + EXTB_OFF_B);
            uint32_t a[2][4];
#pragma unroll
            for (int mt = 0; mt < 2; mt++) {
                int rb = wm * 32 + mt * 16 + gid;
                a[mt][0] = Aw[rb * 8 + l4];
                a[mt][1] = Aw[(rb + 8) * 8 + l4];
                a[mt][2] = Aw[rb * 8 + l4 + 4];
                a[mt][3] = Aw[(rb + 8) * 8 + l4 + 4];
            }
#pragma unroll
            for (int g = 0; g < 2; g++)     // gate n ext rows are zero; skip g=2
#pragma unroll
                for (int nt = 0; nt < 2; nt++) {
                    int rb = g * 32 + wn * 16 + nt * 8 + gid;
                    uint32_t b[2];
                    b[0] = Bw[rb * 8 + l4];
                    b[1] = Bw[rb * 8 + l4 + 4];
                    mma_m16n8k16_f16(acc[g][0][nt], a[0], b);
                    mma_m16n8k16_f16(acc[g][1][nt], a[1], b);
                }
        }

        if (it + 2 < NKT) issue((it + 2) % NSTAGE, (it + 2) * FBK);
        CP_COMMIT();

        const uint32_t* Aw = (const uint32_t*)(smemc + (it % NSTAGE) * A_STG_B);
        const uint32_t* Bw = (const uint32_t*)(smemc + SB_OFF_B + (it % NSTAGE) * B_STG_B);

#pragma unroll
        for (int ks = 0; ks < 2; ks++) {
            const int kw = ks * 8 + l4;     // word offset (FSTH/2 = 20 words/row)
            uint32_t a[2][4];
#pragma unroll
            for (int mt = 0; mt < 2; mt++) {
                int rb = wm * 32 + mt * 16 + gid;
                a[mt][0] = Aw[rb * 20 + kw];
                a[mt][1] = Aw[(rb + 8) * 20 + kw];
                a[mt][2] = Aw[rb * 20 + kw + 4];
                a[mt][3] = Aw[(rb + 8) * 20 + kw + 4];
            }
#pragma unroll
            for (int g = 0; g < 3; g++)
#pragma unroll
                for (int nt = 0; nt < 2; nt++) {
                    int rb = g * 32 + wn * 16 + nt * 8 + gid;
                    uint32_t b[2];
                    b[0] = Bw[rb * 20 + kw];
                    b[1] = Bw[rb * 20 + kw + 4];
                    mma_m16n8k16_f16(acc[g][0][nt], a[0], b);
                    mma_m16n8k16_f16(acc[g][1][nt], a[1], b);
                }
        }
    }

    // ---- epilogue: GRU update (r,u token corr in acc; gate-n corr here) ----
#pragma unroll
    for (int mt = 0; mt < 2; mt++) {
#pragma unroll
        for (int rs = 0; rs < 2; rs++) {
            int rloc = wm * 32 + mt * 16 + gid + rs * 8;
            int grow = m0 + rloc;
            float t0 = s_tok[rloc * 3 + 0];
            float t1 = s_tok[rloc * 3 + 1];
            float t2 = s_tok[rloc * 3 + 2];
            const float* gi = g_gi + (size_t)grow * G3;
            float*  hrow  = g_h  + (size_t)grow * HID;
            __half* hfrow = hdst + (size_t)grow * HID;
#pragma unroll
            for (int nt = 0; nt < 2; nt++) {
                int ul = wn * 16 + nt * 8 + l4 * 2;   // local unit (even)
                int gu = n0 + ul;
                float2 gr  = *(const float2*)(gi + gu);
                float2 gu2 = *(const float2*)(gi + HID + gu);
                float2 gn  = *(const float2*)(gi + 2 * HID + gu);
                float2 h2  = *(const float2*)(hrow + gu);

                float hn_out[2];
#pragma unroll
                for (int c = 0; c < 2; c++) {
                    int u = ul + c;
                    float acc_r = acc[0][mt][nt][rs * 2 + c];
                    float acc_u = acc[1][mt][nt][rs * 2 + c];
                    float acc_n = acc[2][mt][nt][rs * 2 + c];
                    float gi_r = (c ? gr.y  : gr.x);
                    float gi_u = (c ? gu2.y : gu2.x);
                    float gi_n = (c ? gn.y  : gn.x);
                    float hold = (c ? h2.y  : h2.x);

                    // gate n: token correction OUTSIDE the r* product
                    float in_ = gi_n + t0 * s_twn[u * 3 + 0]
                                     + t1 * s_twn[u * 3 + 1]
                                     + t2 * s_twn[u * 3 + 2];

                    float r  = fast_sig(gi_r + acc_r + s_bh[u]);
                    float uu = fast_sig(gi_u + acc_u + s_bh[32 + u]);
                    float n  = fast_tanh(in_ + r * (acc_n + s_bh[64 + u]));
                    hn_out[c] = (1.0f - uu) * n + uu * hold;
                }
                *(float2*)(hrow + gu) = make_float2(hn_out[0], hn_out[1]);
                *(half2*)(hfrow + gu) = __floats2half2_rn(hn_out[0], hn_out[1]);
            }
        }
    }
}

// ---------------------------------------------------------------------------
// Output head (per-row): o = h_new @ W_out^T + b_out; recon + next token.
// ---------------------------------------------------------------------------
__global__ void __launch_bounds__(128)
out_head(const float* __restrict__ W_out,
         const float* __restrict__ b_out,
         float* __restrict__ recon,
         int t)
{
    const int row = blockIdx.x;
    const int tid = threadIdx.x;
    const int lane = tid & 31;
    const int warp = tid >> 5;
    __shared__ float red[3][4];

    const float4* h4 = (const float4*)(g_h + (size_t)row * HID);
    const float4* w0 = (const float4*)(W_out);
    const float4* w1 = (const float4*)(W_out + HID);
    const float4* w2 = (const float4*)(W_out + 2 * HID);

    float s0 = 0.f, s1 = 0.f, s2 = 0.f;
#pragma unroll
    for (int i = 0; i < HID / (128 * 4); i++) {
        int idx = tid + i * 128;
        float4 hv = h4[idx];
        float4 a = w0[idx], b = w1[idx], c = w2[idx];
        s0 += hv.x * a.x + hv.y * a.y + hv.z * a.z + hv.w * a.w;
        s1 += hv.x * b.x + hv.y * b.y + hv.z * b.z + hv.w * b.w;
        s2 += hv.x * c.x + hv.y * c.y + hv.z * c.z + hv.w * c.w;
    }
#pragma unroll
    for (int off = 16; off > 0; off >>= 1) {
        s0 += __shfl_down_sync(0xffffffffu, s0, off);
        s1 += __shfl_down_sync(0xffffffffu, s1, off);
        s2 += __shfl_down_sync(0xffffffffu, s2, off);
    }
    if (lane == 0) { red[0][warp] = s0; red[1][warp] = s1; red[2][warp] = s2; }
    __syncthreads();
    if (tid == 0) {
        float a0 = red[0][0] + red[0][1] + red[0][2] + red[0][3];
        float a1 = red[1][0] + red[1][1] + red[1][2] + red[1][3];
        float a2 = red[2][0] + red[2][1] + red[2][2] + red[2][3];
        float bass    = sigmoidf(a0 + b_out[0]);
        float rhy_int = a1 + b_out[1];
        float rhy     = sigmoidf(a2 + b_out[2]);
        float tok2    = (rhy > 0.5f) ? 1.0f : 0.0f;

        float* rc = recon + (size_t)row * (N_STEP * OUT_DIM) + t * OUT_DIM;
        rc[0] = bass; rc[1] = rhy_int; rc[2] = rhy;

        g_token[row * 3 + 0] = bass;
        g_token[row * 3 + 1] = rhy_int;
        g_token[row * 3 + 2] = tok2;
        __half* tk = g_tokx + (size_t)row * 16;
        tk[0] = __float2half(bass);
        tk[1] = __float2half(rhy_int);
        tk[2] = __float2half(tok2);
    }
}

// ---------------------------------------------------------------------------
// kernel_launch
// inputs: 0 z, 1 inference, 2 tfr, 3 W_zh, 4 b_zh, 5 W_zi, 6 b_zi,
//         7 W_ih, 8 b_ih, 9 W_hh, 10 b_hh, 11 W_out, 12 b_out, 13 init_input
// ---------------------------------------------------------------------------
extern "C" void kernel_launch(void* const* d_in, const int* in_sizes, int n_in,
                              void* d_out, int out_size)
{
    (void)in_sizes; (void)n_in; (void)out_size;

    const float* z      = (const float*)d_in[0];
    const float* W_zh   = (const float*)d_in[3];
    const float* b_zh   = (const float*)d_in[4];
    const float* W_zi   = (const float*)d_in[5];
    const float* b_zi   = (const float*)d_in[6];
    const float* W_ih   = (const float*)d_in[7];
    const float* b_ih   = (const float*)d_in[8];
    const float* W_hh   = (const float*)d_in[9];
    const float* b_hh   = (const float*)d_in[10];
    const float* W_out  = (const float*)d_in[11];
    const float* b_out  = (const float*)d_in[12];
    const float* initin = (const float*)d_in[13];
    float* recon = (float*)d_out;

    float *p_h, *p_gi, *p_zin;
    __half *p_ha, *p_hb;
    cudaGetSymbolAddress((void**)&p_h,   g_h);
    cudaGetSymbolAddress((void**)&p_gi,  g_gi);
    cudaGetSymbolAddress((void**)&p_zin, g_zin);
    cudaGetSymbolAddress((void**)&p_ha,  g_hh_a);
    cudaGetSymbolAddress((void**)&p_hb,  g_hh_b);

    cudaFuncSetAttribute(fused_step, cudaFuncAttributeMaxDynamicSharedMemorySize,
                         FUSED_SMEM_BYTES);

    // 1: setup (token, K-ext weights, gate-n tokw, W_hh fp16)
    setup_kernel<<<192, 256>>>(W_ih, W_hh, initin);
    // 2: h0 (+fp16 dup) and z_in in one dual launch
    gemm_dual<<<dim3(9, BS / BM), 256>>>(z, W_zh, b_zh, W_zi, b_zi, p_h, p_ha, p_zin);
    // 3: gi = z_in @ W_ih[:,3:]^T + b_ih
    gemm_tf32<<<dim3(G3 / BN, BS / BM), 256>>>(p_zin, Z_IN, W_ih + OUT_DIM, X_DIM, b_ih, p_gi, nullptr, BS, G3, Z_IN);

    // 4..: steps (launch #4 = fused_step -> ncu capture slot)
    for (int t = 0; t < N_STEP; t++) {
        const __half* hsrc = (t & 1) ? p_hb : p_ha;
        __half*       hdst = (t & 1) ? p_ha : p_hb;
        fused_step<<<dim3(HID / FBU, BS / FBM), 256, FUSED_SMEM_BYTES>>>(hsrc, hdst, b_hh);
        out_head<<<BS, 128>>>(W_out, b_out, recon, t);
    }
}